// round 15
// baseline (speedup 1.0000x reference)
#include <cuda_runtime.h>
#include <cuda_fp16.h>
#include <math.h>
#include <float.h>

#define NMAX 100000
#define EMAX 1600000
#define CDIM 40

typedef unsigned long long u64;
typedef unsigned int u32;

// ---------------------------------------------------------------------------
// Scratch (device globals; tail kernel restores zero-state each call)
// ---------------------------------------------------------------------------
__device__ __align__(16) __half g_h1[NMAX * 64];
__device__ __align__(16) __half g_h2[NMAX * 64];
__device__ __align__(16) __half g_y [NMAX * 64];
__device__ __align__(16) __half g_z [NMAX * 64];
__device__ int g_deg[NMAX];
__device__ int g_cur[NMAX];
__device__ int g_startArr[NMAX];
__device__ int g_pref[1024];
__device__ int g_colArr[EMAX];

// ---------------------------------------------------------------------------
// Launch 1: degree histogram (deg starts zeroed)
// ---------------------------------------------------------------------------
__global__ void hist_kernel(const int* __restrict__ dst, int* __restrict__ deg, int E) {
    int e = blockIdx.x * blockDim.x + threadIdx.x;
    if (e < E) atomicAdd(&deg[dst[e]], 1);
}

// ---------------------------------------------------------------------------
// Launch 2: single-pass exclusive scan, decoupled lookback (98 blocks, 1 wave)
// ---------------------------------------------------------------------------
__global__ void scan_kernel(const int* __restrict__ deg, int* __restrict__ start,
                            int* __restrict__ pref, int n) {
    const int t = threadIdx.x, b = blockIdx.x;
    const int gid = b * 1024 + t;
    const int v = (gid < n) ? deg[gid] : 0;
    const int lane = t & 31, w = t >> 5;
    int inc = v;
#pragma unroll
    for (int o = 1; o < 32; o <<= 1) {
        int u = __shfl_up_sync(0xffffffffu, inc, o);
        if (lane >= o) inc += u;
    }
    __shared__ int ws[32];
    __shared__ int sPref;
    if (lane == 31) ws[w] = inc;
    __syncthreads();
    if (t < 32) {
        int s = ws[t];
#pragma unroll
        for (int o = 1; o < 32; o <<= 1) {
            int u = __shfl_up_sync(0xffffffffu, s, o);
            if (t >= o) s += u;
        }
        ws[t] = s;
    }
    __syncthreads();
    const int offs  = (w > 0) ? ws[w - 1] : 0;
    const int total = ws[31];
    if (t == 0) {
        int prefix = 0;
        if (b > 0) {
            while ((prefix = atomicAdd(&pref[b], 0)) == 0) __nanosleep(40);
            prefix -= 1;
        }
        atomicExch(&pref[b + 1], prefix + total + 1);
        sPref = prefix;
    }
    __syncthreads();
    if (gid < n) start[gid] = sPref + offs + inc - v;
}

// ---------------------------------------------------------------------------
// mma.sync.m16n8k16 f16xf16 -> f32
// ---------------------------------------------------------------------------
__device__ __forceinline__ void mma16816(float* c, const u32* a, u32 b0, u32 b1) {
    asm volatile(
        "mma.sync.aligned.m16n8k16.row.col.f32.f16.f16.f32 "
        "{%0,%1,%2,%3}, {%4,%5,%6,%7}, {%8,%9}, {%0,%1,%2,%3};\n"
        : "+f"(c[0]), "+f"(c[1]), "+f"(c[2]), "+f"(c[3])
        : "r"(a[0]), "r"(a[1]), "r"(a[2]), "r"(a[3]), "r"(b0), "r"(b1));
}

// cp.async 16B with zero-fill when !valid
__device__ __forceinline__ void cp16(u32 daddr, const void* gsrc, bool valid) {
    int sz = valid ? 16 : 0;
    asm volatile("cp.async.cg.shared.global [%0], [%1], 16, %2;\n"
                 :: "r"(daddr), "l"(gsrc), "r"(sz) : "memory");
}
#define CP_COMMIT() asm volatile("cp.async.commit_group;" ::: "memory")
#define CP_WAIT0()  asm volatile("cp.async.wait_group 0;"  ::: "memory")

// ---------------------------------------------------------------------------
// Weight staging (shared by both gemm variants): combined [2*OUTS][72] fp16
// ---------------------------------------------------------------------------
template <int OUTS>
__device__ __forceinline__ void stage_weights(__half* sW,
                                              const float* __restrict__ Wl,
                                              const float* __restrict__ Wr) {
    for (int idx = threadIdx.x; idx < 2 * OUTS * 64; idx += 256) {
        int n = idx >> 6, k = idx & 63;
        float wv = (n < OUTS) ? Wl[n * 64 + k] : Wr[(n - OUTS) * 64 + k];
        sW[n * 72 + k] = __float2half(wv);
    }
}

// ---------------------------------------------------------------------------
// MMA compute + store for one staged tile (sX fp16[64][72])
// ---------------------------------------------------------------------------
template <int OUTS>
__device__ __forceinline__ void mma_tile(const u32* sWu, const u32* sXu,
                                         const float* __restrict__ bias,
                                         __half* __restrict__ y, __half* __restrict__ z,
                                         int base, int nN) {
    const int tid  = threadIdx.x;
    const int w    = tid >> 5;
    const int lane = tid & 31;
    const int grp  = lane >> 2;
    const int tig  = lane & 3;
    const int mg   = (w & 3) * 16;
    const bool isZ = (w >= 4);
    const int nb0  = isZ ? OUTS : 0;
    constexpr int NT = OUTS / 8;

    u32 A[4][4];
    const int r0 = mg + grp;
#pragma unroll
    for (int ks = 0; ks < 4; ks++) {
        A[ks][0] = sXu[r0 * 36 + ks * 8 + tig];
        A[ks][1] = sXu[(r0 + 8) * 36 + ks * 8 + tig];
        A[ks][2] = sXu[r0 * 36 + ks * 8 + 4 + tig];
        A[ks][3] = sXu[(r0 + 8) * 36 + ks * 8 + 4 + tig];
    }

    float acc[NT][4];
#pragma unroll
    for (int nt = 0; nt < NT; nt++) {
        acc[nt][0] = 0.f; acc[nt][1] = 0.f; acc[nt][2] = 0.f; acc[nt][3] = 0.f;
        const int nrow = nb0 + nt * 8 + grp;
#pragma unroll
        for (int ks = 0; ks < 4; ks++) {
            u32 b0 = sWu[nrow * 36 + ks * 8 + tig];
            u32 b1 = sWu[nrow * 36 + ks * 8 + 4 + tig];
            mma16816(acc[nt], A[ks], b0, b1);
        }
    }

    const int m0   = base + mg + grp;
    const int ncol = tig * 2;
    const bool ok0 = (m0 < nN);
    const bool ok1 = (m0 + 8 < nN);
    if (!isZ) {
#pragma unroll
        for (int nt = 0; nt < NT; nt++) {
            const int n = nt * 8 + ncol;
            if (ok0) *(__half2*)(y + (size_t)m0 * OUTS + n) =
                __floats2half2_rn(acc[nt][0], acc[nt][1]);
            if (ok1) *(__half2*)(y + (size_t)(m0 + 8) * OUTS + n) =
                __floats2half2_rn(acc[nt][2], acc[nt][3]);
        }
    } else {
#pragma unroll
        for (int nt = 0; nt < NT; nt++) {
            const int n = nt * 8 + ncol;
            const float b0v = __ldg(&bias[n]);
            const float b1v = __ldg(&bias[n + 1]);
            if (ok0) *(__half2*)(z + (size_t)m0 * OUTS + n) =
                __floats2half2_rn(acc[nt][0] + b0v, acc[nt][1] + b1v);
            if (ok1) *(__half2*)(z + (size_t)(m0 + 8) * OUTS + n) =
                __floats2half2_rn(acc[nt][2] + b0v, acc[nt][3] + b1v);
        }
    }
}

// ---------------------------------------------------------------------------
// fp16-input gemm (layers 2,3): cp.async double-buffered, 1 barrier per tile.
// SMEM 36.9KB: sW[128][72] | sX0[64][72] | sX1[64][72].
// ---------------------------------------------------------------------------
template <int OUTS>
__launch_bounds__(256)
__global__ void gemm16_kernel(const __half* __restrict__ xin,
                              const float* __restrict__ Wl,
                              const float* __restrict__ Wr,
                              const float* __restrict__ bias,
                              __half* __restrict__ y, __half* __restrict__ z, int nN) {
    extern __shared__ __align__(16) unsigned char smem[];
    __half* sW = (__half*)smem;
    const u32* sWu = (const u32*)sW;
    u32 base_sa;
    asm("{ .reg .u64 t; cvta.to.shared.u64 t, %1; cvt.u32.u64 %0, t; }"
        : "=r"(base_sa) : "l"(smem));
    const u32 sxA[2] = { base_sa + 18432, base_sa + 18432 + 9216 };
    const __half* sXp[2] = { (__half*)(smem + 18432), (__half*)(smem + 18432 + 9216) };

    stage_weights<OUTS>(sW, Wl, Wr);

    const int tid = threadIdx.x;
    const int gn = tid >> 2;            // staging row 0..63
    const int q2 = tid & 3;
    const int nTiles = (nN + 63) >> 6;

    // issue async loads for tile tt into buffer buf
    auto issue = [&](int tt, int buf) {
        const int node = (tt << 6) + gn;
        const bool v = (tt < nTiles) && (node < nN);
        const int nodeC = v ? node : 0;
        const __half* rs = xin + (size_t)nodeC * 64 + q2 * 16;
        const u32 d = sxA[buf] + gn * 144 + q2 * 32;
        cp16(d, rs, v);
        cp16(d + 16, rs + 8, v);
        CP_COMMIT();
    };

    int b = 0;
    issue(blockIdx.x, 0);
    for (int t = blockIdx.x; t < nTiles; t += gridDim.x, b ^= 1) {
        CP_WAIT0();
        __syncthreads();                 // tile t data + buffer b^1 free
        issue(t + gridDim.x, b ^ 1);     // overlap next loads with MMA
        mma_tile<OUTS>(sWu, (const u32*)sXp[b], bias, y, z, t << 6, nN);
    }
}

// ---------------------------------------------------------------------------
// fp32-input gemm body (layer 1, fused with fill): classic 2-sync staging
// ---------------------------------------------------------------------------
__device__ __forceinline__ void gemm32_body(int bb, int gridB,
                                            const float4* __restrict__ xin4,
                                            const float* __restrict__ Wl,
                                            const float* __restrict__ Wr,
                                            const float* __restrict__ bias,
                                            __half* __restrict__ y, __half* __restrict__ z,
                                            int nN, unsigned char* smem) {
    __half* sW = (__half*)smem;
    __half* sX = (__half*)(smem + 18432);
    stage_weights<64>(sW, Wl, Wr);

    const int tid = threadIdx.x;
    const int gn = tid >> 2, q2 = tid & 3;
    const int nTiles = (nN + 63) >> 6;

    for (int t = bb; t < nTiles; t += gridB) {
        __syncthreads();
        const int base = t << 6;
        {
            const int node = base + gn;
            const float4* rs = xin4 + (size_t)node * 16 + q2 * 4;
            __half2 h[8];
#pragma unroll
            for (int c = 0; c < 4; c++) {
                float4 v = {0.f, 0.f, 0.f, 0.f};
                if (node < nN) v = __ldg(rs + c);
                h[c * 2]     = __floats2half2_rn(v.x, v.y);
                h[c * 2 + 1] = __floats2half2_rn(v.z, v.w);
            }
            u32* dx = (u32*)(sX + gn * 72 + q2 * 16);
#pragma unroll
            for (int c = 0; c < 8; c++) dx[c] = ((u32*)h)[c];
        }
        __syncthreads();
        mma_tile<64>((const u32*)sW, (const u32*)sX, bias, y, z, base, nN);
    }
}

// ---------------------------------------------------------------------------
// Launch 3: CSR fill (blocks [0,FB)) + layer-1 gemm (blocks [FB,FB+GB))
// ---------------------------------------------------------------------------
__launch_bounds__(256)
__global__ void fill_gemm1_kernel(const int* __restrict__ src, const int* __restrict__ dst,
                                  const int* __restrict__ start, int* __restrict__ cur,
                                  int* __restrict__ col, int E, int FB,
                                  const float4* __restrict__ xin4,
                                  const float* __restrict__ Wl, const float* __restrict__ Wr,
                                  const float* __restrict__ bias,
                                  __half* __restrict__ y, __half* __restrict__ z,
                                  int nN, int GB) {
    extern __shared__ __align__(16) unsigned char smem[];
    if (blockIdx.x < FB) {
        int e = blockIdx.x * 256 + threadIdx.x;
        if (e < E) {
            int d = dst[e];
            int p = start[d] + atomicAdd(&cur[d], 1);
            col[p] = src[e];
        }
    } else {
        gemm32_body(blockIdx.x - FB, GB, xin4, Wl, Wr, bias, y, z, nN, smem);
    }
}

// ---------------------------------------------------------------------------
// Packed accumulation: half2 -> f32x2 add (2 CVT + 1 packed add per half2)
// ---------------------------------------------------------------------------
__device__ __forceinline__ void addh2(u64& acc, u32 h) {
    asm("{\n\t"
        ".reg .b16 l16, h16;\n\t"
        ".reg .f32 lf, hf;\n\t"
        ".reg .b64 p;\n\t"
        "mov.b32 {l16, h16}, %1;\n\t"
        "cvt.f32.f16 lf, l16;\n\t"
        "cvt.f32.f16 hf, h16;\n\t"
        "mov.b64 p, {lf, hf};\n\t"
        "add.rn.f32x2 %0, %0, p;\n\t"
        "}" : "+l"(acc) : "r"(h));
}
__device__ __forceinline__ void unpack2(float& lo, float& hi, u64 v) {
    asm("mov.b64 {%0, %1}, %2;" : "=f"(lo), "=f"(hi) : "l"(v));
}
__device__ __forceinline__ void accv(u64* a, uint4 v) {
    addh2(a[0], v.x); addh2(a[1], v.y); addh2(a[2], v.z); addh2(a[3], v.w);
}

// ---------------------------------------------------------------------------
// Gather (hidden layers, 64-d): h = fp16(relu(mean y + z))
// ---------------------------------------------------------------------------
__launch_bounds__(256)
__global__ void gather64_kernel(const __half* __restrict__ y,
                                const __half* __restrict__ z,
                                const int* __restrict__ start,
                                const int* __restrict__ deg,
                                const int* __restrict__ col,
                                __half* __restrict__ out, int nN) {
    const int node = blockIdx.x * 32 + (threadIdx.x >> 3);
    const int q = threadIdx.x & 7;
    if (node >= nN) return;

    const int d  = __ldg(&deg[node]);
    const int p0 = __ldg(&start[node]);

    u64 a[4] = {0ull, 0ull, 0ull, 0ull};
    int i = 0;
    for (; i + 4 <= d; i += 4) {
        int n0 = __ldg(&col[p0 + i]);
        int n1 = __ldg(&col[p0 + i + 1]);
        int n2 = __ldg(&col[p0 + i + 2]);
        int n3 = __ldg(&col[p0 + i + 3]);
        uint4 v0 = __ldg((const uint4*)(y + (size_t)n0 * 64) + q);
        uint4 v1 = __ldg((const uint4*)(y + (size_t)n1 * 64) + q);
        uint4 v2 = __ldg((const uint4*)(y + (size_t)n2 * 64) + q);
        uint4 v3 = __ldg((const uint4*)(y + (size_t)n3 * 64) + q);
        accv(a, v0); accv(a, v1); accv(a, v2); accv(a, v3);
    }
    for (; i < d; i++) {
        int n0 = __ldg(&col[p0 + i]);
        uint4 v0 = __ldg((const uint4*)(y + (size_t)n0 * 64) + q);
        accv(a, v0);
    }

    const float iv = 1.0f / fmaxf((float)d, 1.0f);
    uint4 zc = __ldg((const uint4*)(z + (size_t)node * 64) + q);
    const u32* zcu = (const u32*)&zc;
    __half2 r[4];
#pragma unroll
    for (int c = 0; c < 4; c++) {
        float f0, f1;
        unpack2(f0, f1, a[c]);
        float2 zf = __half22float2(*(const __half2*)&zcu[c]);
        float r0 = fmaxf(f0 * iv + zf.x, 0.f);
        float r1 = fmaxf(f1 * iv + zf.y, 0.f);
        r[c] = __floats2half2_rn(r0, r1);
    }
    *((uint4*)(out + (size_t)node * 64) + q) = *(uint4*)r;
}

// ---------------------------------------------------------------------------
// Final gather + fused log_softmax (40-d; 5 active chunks of 8; fp32 out)
// ---------------------------------------------------------------------------
__launch_bounds__(256)
__global__ void gather_lsm_kernel(const __half* __restrict__ y,
                                  const __half* __restrict__ z,
                                  const int* __restrict__ start,
                                  const int* __restrict__ deg,
                                  const int* __restrict__ col,
                                  float* __restrict__ out, int nN) {
    const int node = blockIdx.x * 32 + (threadIdx.x >> 3);
    const int q = threadIdx.x & 7;
    const bool valid = (node < nN) && (q < 5);

    int d = 0, p0 = 0;
    if (valid) { d = __ldg(&deg[node]); p0 = __ldg(&start[node]); }

    u64 a[4] = {0ull, 0ull, 0ull, 0ull};
    int i = 0;
    for (; i + 4 <= d; i += 4) {
        int n0 = __ldg(&col[p0 + i]);
        int n1 = __ldg(&col[p0 + i + 1]);
        int n2 = __ldg(&col[p0 + i + 2]);
        int n3 = __ldg(&col[p0 + i + 3]);
        uint4 v0 = __ldg((const uint4*)(y + (size_t)n0 * 40) + q);
        uint4 v1 = __ldg((const uint4*)(y + (size_t)n1 * 40) + q);
        uint4 v2 = __ldg((const uint4*)(y + (size_t)n2 * 40) + q);
        uint4 v3 = __ldg((const uint4*)(y + (size_t)n3 * 40) + q);
        accv(a, v0); accv(a, v1); accv(a, v2); accv(a, v3);
    }
    for (; i < d; i++) {
        int n0 = __ldg(&col[p0 + i]);
        uint4 v0 = __ldg((const uint4*)(y + (size_t)n0 * 40) + q);
        accv(a, v0);
    }

    float v[8];
    float m = -FLT_MAX;
    if (valid) {
        const float iv = 1.0f / fmaxf((float)d, 1.0f);
        uint4 zc = __ldg((const uint4*)(z + (size_t)node * 40) + q);
        const u32* zcu = (const u32*)&zc;
#pragma unroll
        for (int c = 0; c < 4; c++) {
            float f0, f1;
            unpack2(f0, f1, a[c]);
            float2 zf = __half22float2(*(const __half2*)&zcu[c]);
            v[c * 2]     = f0 * iv + zf.x;
            v[c * 2 + 1] = f1 * iv + zf.y;
        }
#pragma unroll
        for (int k2 = 0; k2 < 8; k2++) m = fmaxf(m, v[k2]);
    }
    m = fmaxf(m, __shfl_xor_sync(0xffffffffu, m, 1));
    m = fmaxf(m, __shfl_xor_sync(0xffffffffu, m, 2));
    m = fmaxf(m, __shfl_xor_sync(0xffffffffu, m, 4));

    float s = 0.f;
    if (valid) {
#pragma unroll
        for (int k2 = 0; k2 < 8; k2++) s += __expf(v[k2] - m);
    }
    s += __shfl_xor_sync(0xffffffffu, s, 1);
    s += __shfl_xor_sync(0xffffffffu, s, 2);
    s += __shfl_xor_sync(0xffffffffu, s, 4);

    if (valid) {
        const float l = m + __logf(s);
        float* orow = out + (size_t)node * 40 + q * 8;
        float4 r0, r1;
        r0.x = v[0] - l; r0.y = v[1] - l; r0.z = v[2] - l; r0.w = v[3] - l;
        r1.x = v[4] - l; r1.y = v[5] - l; r1.z = v[6] - l; r1.w = v[7] - l;
        *(float4*)orow       = r0;
        *(float4*)(orow + 4) = r1;
    }
}

// ---------------------------------------------------------------------------
// Tail: restore zero-state for next call
// ---------------------------------------------------------------------------
__global__ void tail_kernel(int* __restrict__ deg, int* __restrict__ cur,
                            int* __restrict__ pref, int n) {
    int i = blockIdx.x * blockDim.x + threadIdx.x;
    if (i < n) { deg[i] = 0; cur[i] = 0; }
    if (i < 1024) pref[i] = 0;
}

// ---------------------------------------------------------------------------
// kernel_launch — slot 4 = gather64 layer 1 (the ncu-profiled launch)
// ---------------------------------------------------------------------------
extern "C" void kernel_launch(void* const* d_in, const int* in_sizes, int n_in,
                              void* d_out, int out_size) {
    const float* x   = (const float*)d_in[0];
    const int*   ei  = (const int*)d_in[1];
    const float* Wl1 = (const float*)d_in[2];
    const float* Wr1 = (const float*)d_in[3];
    const float* b1  = (const float*)d_in[4];
    const float* Wl2 = (const float*)d_in[5];
    const float* Wr2 = (const float*)d_in[6];
    const float* b2  = (const float*)d_in[7];
    const float* Wl3 = (const float*)d_in[8];
    const float* Wr3 = (const float*)d_in[9];
    const float* b3  = (const float*)d_in[10];
    float* out = (float*)d_out;

    const int N = in_sizes[0] / 64;
    const int E = in_sizes[1] / 2;
    const int* src = ei;
    const int* dst = ei + E;

    int *deg, *cur, *start, *pref, *col;
    __half *h1, *h2, *y, *z;
    cudaGetSymbolAddress((void**)&deg,   g_deg);
    cudaGetSymbolAddress((void**)&cur,   g_cur);
    cudaGetSymbolAddress((void**)&start, g_startArr);
    cudaGetSymbolAddress((void**)&pref,  g_pref);
    cudaGetSymbolAddress((void**)&col,   g_colArr);
    cudaGetSymbolAddress((void**)&h1,    g_h1);
    cudaGetSymbolAddress((void**)&h2,    g_h2);
    cudaGetSymbolAddress((void**)&y,     g_y);
    cudaGetSymbolAddress((void**)&z,     g_z);

    const int SMEM1 = 18432 + 9216;          // fp32 gemm (single sX)
    const int SMEM2 = 18432 + 2 * 9216;      // fp16 gemm (double-buffered)
    const int nb    = (N + 1023) / 1024;
    const int edgeB = (E + 255) / 256;
    const int GB    = 592;
    const int gathB = (N + 31) / 32;

    hist_kernel<<<edgeB, 256>>>(dst, deg, E);                       // 1
    scan_kernel<<<nb, 1024>>>(deg, start, pref, N);                 // 2
    fill_gemm1_kernel<<<edgeB + GB, 256, SMEM1>>>(src, dst, start, cur, col, E, edgeB,
                                                  (const float4*)x, Wl1, Wr1, b1,
                                                  y, z, N, GB);     // 3
    gather64_kernel<<<gathB, 256>>>(y, z, start, deg, col, h1, N);  // 4 (PROFILED)
    gemm16_kernel<64><<<GB, 256, SMEM2>>>(h1, Wl2, Wr2, b2, y, z, N);  // 5
    gather64_kernel<<<gathB, 256>>>(y, z, start, deg, col, h2, N);  // 6
    gemm16_kernel<40><<<GB, 256, SMEM2>>>(h2, Wl3, Wr3, b3, y, z, N);  // 7
    gather_lsm_kernel<<<gathB, 256>>>(y, z, start, deg, col, out, N);  // 8
    tail_kernel<<<(N + 255) / 256, 256>>>(deg, cur, pref, N);       // 9
}

// round 16
// speedup vs baseline: 1.0856x; 1.0856x over previous
#include <cuda_runtime.h>
#include <cuda_fp16.h>
#include <math.h>
#include <float.h>

#define NMAX 100000
#define EMAX 1600000
#define CDIM 40

typedef unsigned long long u64;
typedef unsigned int u32;

// ---------------------------------------------------------------------------
// Scratch (device globals; tail kernel restores zero-state each call)
// ---------------------------------------------------------------------------
__device__ __align__(16) __half g_h1[NMAX * 64];
__device__ __align__(16) __half g_h2[NMAX * 64];
__device__ __align__(16) __half g_y [NMAX * 64];
__device__ __align__(16) __half g_z [NMAX * 64];
__device__ int g_deg[NMAX];
__device__ int g_cur[NMAX];
__device__ int g_startArr[NMAX];
__device__ int g_pref[1024];
__device__ int g_colArr[EMAX];

// ---------------------------------------------------------------------------
// Launch 1: degree histogram (deg starts zeroed)
// ---------------------------------------------------------------------------
__global__ void hist_kernel(const int* __restrict__ dst, int* __restrict__ deg, int E) {
    int e = blockIdx.x * blockDim.x + threadIdx.x;
    if (e < E) atomicAdd(&deg[dst[e]], 1);
}

// ---------------------------------------------------------------------------
// Launch 2: single-pass exclusive scan, decoupled lookback (98 blocks, 1 wave)
// ---------------------------------------------------------------------------
__global__ void scan_kernel(const int* __restrict__ deg, int* __restrict__ start,
                            int* __restrict__ pref, int n) {
    const int t = threadIdx.x, b = blockIdx.x;
    const int gid = b * 1024 + t;
    const int v = (gid < n) ? deg[gid] : 0;
    const int lane = t & 31, w = t >> 5;
    int inc = v;
#pragma unroll
    for (int o = 1; o < 32; o <<= 1) {
        int u = __shfl_up_sync(0xffffffffu, inc, o);
        if (lane >= o) inc += u;
    }
    __shared__ int ws[32];
    __shared__ int sPref;
    if (lane == 31) ws[w] = inc;
    __syncthreads();
    if (t < 32) {
        int s = ws[t];
#pragma unroll
        for (int o = 1; o < 32; o <<= 1) {
            int u = __shfl_up_sync(0xffffffffu, s, o);
            if (t >= o) s += u;
        }
        ws[t] = s;
    }
    __syncthreads();
    const int offs  = (w > 0) ? ws[w - 1] : 0;
    const int total = ws[31];
    if (t == 0) {
        int prefix = 0;
        if (b > 0) {
            while ((prefix = atomicAdd(&pref[b], 0)) == 0) __nanosleep(40);
            prefix -= 1;
        }
        atomicExch(&pref[b + 1], prefix + total + 1);
        sPref = prefix;
    }
    __syncthreads();
    if (gid < n) start[gid] = sPref + offs + inc - v;
}

// ---------------------------------------------------------------------------
// mma.sync.m16n8k16 f16xf16 -> f32
// ---------------------------------------------------------------------------
__device__ __forceinline__ void mma16816(float* c, const u32* a, u32 b0, u32 b1) {
    asm volatile(
        "mma.sync.aligned.m16n8k16.row.col.f32.f16.f16.f32 "
        "{%0,%1,%2,%3}, {%4,%5,%6,%7}, {%8,%9}, {%0,%1,%2,%3};\n"
        : "+f"(c[0]), "+f"(c[1]), "+f"(c[2]), "+f"(c[3])
        : "r"(a[0]), "r"(a[1]), "r"(a[2]), "r"(a[3]), "r"(b0), "r"(b1));
}

// ---------------------------------------------------------------------------
// Tensor-core dual dense transform body (R13-proven): y = fp16(x@Wl^T),
// z = fp16(x@Wr^T + b). Tile 64 nodes, 256 threads.
// SMEM 27.6KB: sW fp16[128][72], sX fp16[64][72].
// ---------------------------------------------------------------------------
template <int OUTS, bool FP16IN>
__device__ __forceinline__ void gemm_body(int bb, int gridB,
                                          const void* __restrict__ xin,
                                          const float* __restrict__ Wl,
                                          const float* __restrict__ Wr,
                                          const float* __restrict__ bias,
                                          __half* __restrict__ y,
                                          __half* __restrict__ z,
                                          int nN, unsigned char* smem) {
    __half* sW = (__half*)smem;              // 128 * 72 halves = 18432 B
    __half* sX = (__half*)(smem + 18432);    //  64 * 72 halves =  9216 B

    const int tid = threadIdx.x;
    constexpr int NT = OUTS / 8;

    for (int idx = tid; idx < 2 * OUTS * 64; idx += 256) {
        int n = idx >> 6, k = idx & 63;
        float wv = (n < OUTS) ? Wl[n * 64 + k] : Wr[(n - OUTS) * 64 + k];
        sW[n * 72 + k] = __float2half(wv);
    }

    const int w    = tid >> 5;
    const int lane = tid & 31;
    const int grp  = lane >> 2;
    const int tig  = lane & 3;
    const int mg   = (w & 3) * 16;
    const bool isZ = (w >= 4);
    const int nb0  = isZ ? OUTS : 0;

    const int gn = tid >> 2;                 // staging row 0..63
    const int q2 = tid & 3;

    const u32* sWu = (const u32*)sW;         // row stride 36 u32
    const u32* sXu = (const u32*)sX;

    const int nTiles = (nN + 63) >> 6;
    for (int t = bb; t < nTiles; t += gridB) {
        __syncthreads();
        const int base = t << 6;

        // Stage 64 node rows into sX
        {
            const int node = base + gn;
            if (FP16IN) {
                const uint4* rs = (const uint4*)xin + (size_t)node * 8 + q2 * 2;
                uint4 v0 = {0,0,0,0}, v1 = {0,0,0,0};
                if (node < nN) { v0 = __ldg(rs); v1 = __ldg(rs + 1); }
                uint4* dx = (uint4*)(sX + gn * 72 + q2 * 16);
                dx[0] = v0; dx[1] = v1;
            } else {
                const float4* rs = (const float4*)xin + (size_t)node * 16 + q2 * 4;
                __half2 h[8];
#pragma unroll
                for (int c = 0; c < 4; c++) {
                    float4 v = {0.f, 0.f, 0.f, 0.f};
                    if (node < nN) v = __ldg(rs + c);
                    h[c * 2]     = __floats2half2_rn(v.x, v.y);
                    h[c * 2 + 1] = __floats2half2_rn(v.z, v.w);
                }
                u32* dx = (u32*)(sX + gn * 72 + q2 * 16);
#pragma unroll
                for (int c = 0; c < 8; c++) dx[c] = ((u32*)h)[c];
            }
        }
        __syncthreads();

        u32 A[4][4];
        {
            const int r0 = mg + grp;
#pragma unroll
            for (int ks = 0; ks < 4; ks++) {
                A[ks][0] = sXu[r0 * 36 + ks * 8 + tig];
                A[ks][1] = sXu[(r0 + 8) * 36 + ks * 8 + tig];
                A[ks][2] = sXu[r0 * 36 + ks * 8 + 4 + tig];
                A[ks][3] = sXu[(r0 + 8) * 36 + ks * 8 + 4 + tig];
            }
        }

        float acc[NT][4];
#pragma unroll
        for (int nt = 0; nt < NT; nt++) {
            acc[nt][0] = 0.f; acc[nt][1] = 0.f; acc[nt][2] = 0.f; acc[nt][3] = 0.f;
            const int nrow = nb0 + nt * 8 + grp;
#pragma unroll
            for (int ks = 0; ks < 4; ks++) {
                u32 b0 = sWu[nrow * 36 + ks * 8 + tig];
                u32 b1 = sWu[nrow * 36 + ks * 8 + 4 + tig];
                mma16816(acc[nt], A[ks], b0, b1);
            }
        }

        const int m0   = base + mg + grp;
        const int ncol = tig * 2;
        const bool ok0 = (m0 < nN);
        const bool ok1 = (m0 + 8 < nN);
        if (!isZ) {
#pragma unroll
            for (int nt = 0; nt < NT; nt++) {
                const int n = nt * 8 + ncol;
                if (ok0) *(__half2*)(y + (size_t)m0 * OUTS + n) =
                    __floats2half2_rn(acc[nt][0], acc[nt][1]);
                if (ok1) *(__half2*)(y + (size_t)(m0 + 8) * OUTS + n) =
                    __floats2half2_rn(acc[nt][2], acc[nt][3]);
            }
        } else {
#pragma unroll
            for (int nt = 0; nt < NT; nt++) {
                const int n = nt * 8 + ncol;
                const float b0v = __ldg(&bias[n]);
                const float b1v = __ldg(&bias[n + 1]);
                if (ok0) *(__half2*)(z + (size_t)m0 * OUTS + n) =
                    __floats2half2_rn(acc[nt][0] + b0v, acc[nt][1] + b1v);
                if (ok1) *(__half2*)(z + (size_t)(m0 + 8) * OUTS + n) =
                    __floats2half2_rn(acc[nt][2] + b0v, acc[nt][3] + b1v);
            }
        }
    }
}

template <int OUTS, bool FP16IN>
__launch_bounds__(256)
__global__ void gemm_dual_mma_kernel(const void* __restrict__ xin,
                                     const float* __restrict__ Wl,
                                     const float* __restrict__ Wr,
                                     const float* __restrict__ bias,
                                     __half* __restrict__ y, __half* __restrict__ z,
                                     int nN) {
    extern __shared__ __align__(16) unsigned char smem[];
    gemm_body<OUTS, FP16IN>(blockIdx.x, gridDim.x, xin, Wl, Wr, bias, y, z, nN, smem);
}

// ---------------------------------------------------------------------------
// Launch 3: CSR fill (blocks [0,FB)) + layer-1 gemm (blocks [FB,FB+GB))
// ---------------------------------------------------------------------------
__launch_bounds__(256)
__global__ void fill_gemm1_kernel(const int* __restrict__ src, const int* __restrict__ dst,
                                  const int* __restrict__ start, int* __restrict__ cur,
                                  int* __restrict__ col, int E, int FB,
                                  const float4* __restrict__ xin4,
                                  const float* __restrict__ Wl, const float* __restrict__ Wr,
                                  const float* __restrict__ bias,
                                  __half* __restrict__ y, __half* __restrict__ z,
                                  int nN, int GB) {
    extern __shared__ __align__(16) unsigned char smem[];
    if (blockIdx.x < FB) {
        int e = blockIdx.x * 256 + threadIdx.x;
        if (e < E) {
            int d = dst[e];
            int p = start[d] + atomicAdd(&cur[d], 1);
            col[p] = src[e];
        }
    } else {
        gemm_body<64, false>(blockIdx.x - FB, GB, xin4, Wl, Wr, bias, y, z, nN, smem);
    }
}

// ---------------------------------------------------------------------------
// fp16 helpers (R13-proven fp32 accumulate + new pairwise fp16 pre-add)
// ---------------------------------------------------------------------------
__device__ __forceinline__ void acc8(float* a, uint4 v) {
    float2 f;
    f = __half22float2(*(const __half2*)&v.x); a[0] += f.x; a[1] += f.y;
    f = __half22float2(*(const __half2*)&v.y); a[2] += f.x; a[3] += f.y;
    f = __half22float2(*(const __half2*)&v.z); a[4] += f.x; a[5] += f.y;
    f = __half22float2(*(const __half2*)&v.w); a[6] += f.x; a[7] += f.y;
}
// pairwise fp16 add of two uint4 chunks (4x HADD2)
__device__ __forceinline__ uint4 hadd2v(uint4 a, uint4 b) {
    uint4 r;
    asm("add.rn.f16x2 %0, %1, %2;" : "=r"(r.x) : "r"(a.x), "r"(b.x));
    asm("add.rn.f16x2 %0, %1, %2;" : "=r"(r.y) : "r"(a.y), "r"(b.y));
    asm("add.rn.f16x2 %0, %1, %2;" : "=r"(r.z) : "r"(a.z), "r"(b.z));
    asm("add.rn.f16x2 %0, %1, %2;" : "=r"(r.w) : "r"(a.w), "r"(b.w));
    return r;
}

// ---------------------------------------------------------------------------
// Gather (hidden layers, 64-d): h = fp16(relu(mean y + z))
// 8 threads/node, 1 uint4 chunk each; 4-neighbor unroll with pairwise
// fp16 pre-add (halves CVT+FADD count in the issue-bound hot loop).
// ---------------------------------------------------------------------------
__launch_bounds__(256)
__global__ void gather64_kernel(const __half* __restrict__ y,
                                const __half* __restrict__ z,
                                const int* __restrict__ start,
                                const int* __restrict__ deg,
                                const int* __restrict__ col,
                                __half* __restrict__ out, int nN) {
    const int node = blockIdx.x * 32 + (threadIdx.x >> 3);
    const int q = threadIdx.x & 7;
    if (node >= nN) return;

    const int d  = __ldg(&deg[node]);
    const int p0 = __ldg(&start[node]);

    float a[8] = {0.f,0.f,0.f,0.f,0.f,0.f,0.f,0.f};
    int i = 0;
    for (; i + 4 <= d; i += 4) {
        int n0 = __ldg(&col[p0 + i]);
        int n1 = __ldg(&col[p0 + i + 1]);
        int n2 = __ldg(&col[p0 + i + 2]);
        int n3 = __ldg(&col[p0 + i + 3]);
        uint4 v0 = __ldg((const uint4*)(y + (size_t)n0 * 64) + q);
        uint4 v1 = __ldg((const uint4*)(y + (size_t)n1 * 64) + q);
        uint4 v2 = __ldg((const uint4*)(y + (size_t)n2 * 64) + q);
        uint4 v3 = __ldg((const uint4*)(y + (size_t)n3 * 64) + q);
        acc8(a, hadd2v(v0, v1));
        acc8(a, hadd2v(v2, v3));
    }
    for (; i < d; i++) {
        int n0 = __ldg(&col[p0 + i]);
        uint4 v0 = __ldg((const uint4*)(y + (size_t)n0 * 64) + q);
        acc8(a, v0);
    }

    const float iv = 1.0f / fmaxf((float)d, 1.0f);
    uint4 zc = __ldg((const uint4*)(z + (size_t)node * 64) + q);
    float zf[8];
    {
        float2 f;
        f = __half22float2(*(const __half2*)&zc.x); zf[0] = f.x; zf[1] = f.y;
        f = __half22float2(*(const __half2*)&zc.y); zf[2] = f.x; zf[3] = f.y;
        f = __half22float2(*(const __half2*)&zc.z); zf[4] = f.x; zf[5] = f.y;
        f = __half22float2(*(const __half2*)&zc.w); zf[6] = f.x; zf[7] = f.y;
    }
    __half2 r[4];
#pragma unroll
    for (int c = 0; c < 4; c++) {
        float r0 = fmaxf(a[c*2]   * iv + zf[c*2],   0.f);
        float r1 = fmaxf(a[c*2+1] * iv + zf[c*2+1], 0.f);
        r[c] = __floats2half2_rn(r0, r1);
    }
    *((uint4*)(out + (size_t)node * 64) + q) = *(uint4*)r;
}

// ---------------------------------------------------------------------------
// Final gather + fused log_softmax (40-d; 5 active chunks of 8; fp32 out)
// ---------------------------------------------------------------------------
__launch_bounds__(256)
__global__ void gather_lsm_kernel(const __half* __restrict__ y,
                                  const __half* __restrict__ z,
                                  const int* __restrict__ start,
                                  const int* __restrict__ deg,
                                  const int* __restrict__ col,
                                  float* __restrict__ out, int nN) {
    const int node = blockIdx.x * 32 + (threadIdx.x >> 3);
    const int q = threadIdx.x & 7;
    const bool valid = (node < nN) && (q < 5);

    int d = 0, p0 = 0;
    if (valid) { d = __ldg(&deg[node]); p0 = __ldg(&start[node]); }

    float a[8] = {0.f,0.f,0.f,0.f,0.f,0.f,0.f,0.f};
    int i = 0;
    for (; i + 4 <= d; i += 4) {
        int n0 = __ldg(&col[p0 + i]);
        int n1 = __ldg(&col[p0 + i + 1]);
        int n2 = __ldg(&col[p0 + i + 2]);
        int n3 = __ldg(&col[p0 + i + 3]);
        uint4 v0 = __ldg((const uint4*)(y + (size_t)n0 * 40) + q);
        uint4 v1 = __ldg((const uint4*)(y + (size_t)n1 * 40) + q);
        uint4 v2 = __ldg((const uint4*)(y + (size_t)n2 * 40) + q);
        uint4 v3 = __ldg((const uint4*)(y + (size_t)n3 * 40) + q);
        acc8(a, hadd2v(v0, v1));
        acc8(a, hadd2v(v2, v3));
    }
    for (; i < d; i++) {
        int n0 = __ldg(&col[p0 + i]);
        uint4 v0 = __ldg((const uint4*)(y + (size_t)n0 * 40) + q);
        acc8(a, v0);
    }

    float v[8];
    float m = -FLT_MAX;
    if (valid) {
        const float iv = 1.0f / fmaxf((float)d, 1.0f);
        uint4 zc = __ldg((const uint4*)(z + (size_t)node * 40) + q);
        const u32* zcu = (const u32*)&zc;
#pragma unroll
        for (int c = 0; c < 4; c++) {
            float2 zf = __half22float2(*(const __half2*)&zcu[c]);
            v[c * 2]     = a[c * 2]     * iv + zf.x;
            v[c * 2 + 1] = a[c * 2 + 1] * iv + zf.y;
        }
#pragma unroll
        for (int k2 = 0; k2 < 8; k2++) m = fmaxf(m, v[k2]);
    }
    m = fmaxf(m, __shfl_xor_sync(0xffffffffu, m, 1));
    m = fmaxf(m, __shfl_xor_sync(0xffffffffu, m, 2));
    m = fmaxf(m, __shfl_xor_sync(0xffffffffu, m, 4));

    float s = 0.f;
    if (valid) {
#pragma unroll
        for (int k2 = 0; k2 < 8; k2++) s += __expf(v[k2] - m);
    }
    s += __shfl_xor_sync(0xffffffffu, s, 1);
    s += __shfl_xor_sync(0xffffffffu, s, 2);
    s += __shfl_xor_sync(0xffffffffu, s, 4);

    if (valid) {
        const float l = m + __logf(s);
        float* orow = out + (size_t)node * 40 + q * 8;
        float4 r0, r1;
        r0.x = v[0] - l; r0.y = v[1] - l; r0.z = v[2] - l; r0.w = v[3] - l;
        r1.x = v[4] - l; r1.y = v[5] - l; r1.z = v[6] - l; r1.w = v[7] - l;
        *(float4*)orow       = r0;
        *(float4*)(orow + 4) = r1;
    }
}

// ---------------------------------------------------------------------------
// Tail: restore zero-state for next call
// ---------------------------------------------------------------------------
__global__ void tail_kernel(int* __restrict__ deg, int* __restrict__ cur,
                            int* __restrict__ pref, int n) {
    int i = blockIdx.x * blockDim.x + threadIdx.x;
    if (i < n) { deg[i] = 0; cur[i] = 0; }
    if (i < 1024) pref[i] = 0;
}

// ---------------------------------------------------------------------------
// kernel_launch — slot 4 = gather64 layer 1 (the ncu-profiled launch)
// ---------------------------------------------------------------------------
extern "C" void kernel_launch(void* const* d_in, const int* in_sizes, int n_in,
                              void* d_out, int out_size) {
    const float* x   = (const float*)d_in[0];
    const int*   ei  = (const int*)d_in[1];
    const float* Wl1 = (const float*)d_in[2];
    const float* Wr1 = (const float*)d_in[3];
    const float* b1  = (const float*)d_in[4];
    const float* Wl2 = (const float*)d_in[5];
    const float* Wr2 = (const float*)d_in[6];
    const float* b2  = (const float*)d_in[7];
    const float* Wl3 = (const float*)d_in[8];
    const float* Wr3 = (const float*)d_in[9];
    const float* b3  = (const float*)d_in[10];
    float* out = (float*)d_out;

    const int N = in_sizes[0] / 64;
    const int E = in_sizes[1] / 2;
    const int* src = ei;
    const int* dst = ei + E;

    int *deg, *cur, *start, *pref, *col;
    __half *h1, *h2, *y, *z;
    cudaGetSymbolAddress((void**)&deg,   g_deg);
    cudaGetSymbolAddress((void**)&cur,   g_cur);
    cudaGetSymbolAddress((void**)&start, g_startArr);
    cudaGetSymbolAddress((void**)&pref,  g_pref);
    cudaGetSymbolAddress((void**)&col,   g_colArr);
    cudaGetSymbolAddress((void**)&h1,    g_h1);
    cudaGetSymbolAddress((void**)&h2,    g_h2);
    cudaGetSymbolAddress((void**)&y,     g_y);
    cudaGetSymbolAddress((void**)&z,     g_z);

    const int SMEM  = 18432 + 9216;   // 27.6 KB
    const int nb    = (N + 1023) / 1024;
    const int edgeB = (E + 255) / 256;
    const int GB    = 592;
    const int gathB = (N + 31) / 32;

    hist_kernel<<<edgeB, 256>>>(dst, deg, E);                       // 1
    scan_kernel<<<nb, 1024>>>(deg, start, pref, N);                 // 2
    fill_gemm1_kernel<<<edgeB + GB, 256, SMEM>>>(src, dst, start, cur, col, E, edgeB,
                                                 (const float4*)x, Wl1, Wr1, b1,
                                                 y, z, N, GB);      // 3
    gather64_kernel<<<gathB, 256>>>(y, z, start, deg, col, h1, N);  // 4 (PROFILED)
    gemm_dual_mma_kernel<64, true><<<GB, 256, SMEM>>>(h1, Wl2, Wr2, b2, y, z, N);  // 5
    gather64_kernel<<<gathB, 256>>>(y, z, start, deg, col, h2, N);  // 6
    gemm_dual_mma_kernel<40, true><<<GB, 256, SMEM>>>(h2, Wl3, Wr3, b3, y, z, N);  // 7
    gather_lsm_kernel<<<gathB, 256>>>(y, z, start, deg, col, out, N);              // 8
    tail_kernel<<<(N + 255) / 256, 256>>>(deg, cur, pref, N);       // 9
}

// round 17
// speedup vs baseline: 1.1078x; 1.0205x over previous
#include <cuda_runtime.h>
#include <cuda_fp16.h>
#include <math.h>
#include <float.h>

#define NMAX 100000
#define EMAX 1600000
#define CDIM 40

typedef unsigned long long u64;
typedef unsigned int u32;

// ---------------------------------------------------------------------------
// Scratch (device globals; tail kernel restores zero-state each call)
// Ping-pong fp16 buffers: (g_y,g_z) <-> (g_h1,g_h2)
// ---------------------------------------------------------------------------
__device__ __align__(16) __half g_h1[NMAX * 64];
__device__ __align__(16) __half g_h2[NMAX * 64];
__device__ __align__(16) __half g_y [NMAX * 64];
__device__ __align__(16) __half g_z [NMAX * 64];
__device__ int g_deg[NMAX];
__device__ int g_cur[NMAX];
__device__ int g_startArr[NMAX];
__device__ int g_pref[1024];
__device__ int g_colArr[EMAX];

// ---------------------------------------------------------------------------
// Launch 1: degree histogram (deg starts zeroed)
// ---------------------------------------------------------------------------
__global__ void hist_kernel(const int* __restrict__ dst, int* __restrict__ deg, int E) {
    int e = blockIdx.x * blockDim.x + threadIdx.x;
    if (e < E) atomicAdd(&deg[dst[e]], 1);
}

// ---------------------------------------------------------------------------
// Launch 2: single-pass exclusive scan, decoupled lookback (98 blocks, 1 wave)
// ---------------------------------------------------------------------------
__global__ void scan_kernel(const int* __restrict__ deg, int* __restrict__ start,
                            int* __restrict__ pref, int n) {
    const int t = threadIdx.x, b = blockIdx.x;
    const int gid = b * 1024 + t;
    const int v = (gid < n) ? deg[gid] : 0;
    const int lane = t & 31, w = t >> 5;
    int inc = v;
#pragma unroll
    for (int o = 1; o < 32; o <<= 1) {
        int u = __shfl_up_sync(0xffffffffu, inc, o);
        if (lane >= o) inc += u;
    }
    __shared__ int ws[32];
    __shared__ int sPref;
    if (lane == 31) ws[w] = inc;
    __syncthreads();
    if (t < 32) {
        int s = ws[t];
#pragma unroll
        for (int o = 1; o < 32; o <<= 1) {
            int u = __shfl_up_sync(0xffffffffu, s, o);
            if (t >= o) s += u;
        }
        ws[t] = s;
    }
    __syncthreads();
    const int offs  = (w > 0) ? ws[w - 1] : 0;
    const int total = ws[31];
    if (t == 0) {
        int prefix = 0;
        if (b > 0) {
            while ((prefix = atomicAdd(&pref[b], 0)) == 0) __nanosleep(40);
            prefix -= 1;
        }
        atomicExch(&pref[b + 1], prefix + total + 1);
        sPref = prefix;
    }
    __syncthreads();
    if (gid < n) start[gid] = sPref + offs + inc - v;
}

// ---------------------------------------------------------------------------
// mma.sync.m16n8k16 f16xf16 -> f32
// ---------------------------------------------------------------------------
__device__ __forceinline__ void mma16816(float* c, const u32* a, u32 b0, u32 b1) {
    asm volatile(
        "mma.sync.aligned.m16n8k16.row.col.f32.f16.f16.f32 "
        "{%0,%1,%2,%3}, {%4,%5,%6,%7}, {%8,%9}, {%0,%1,%2,%3};\n"
        : "+f"(c[0]), "+f"(c[1]), "+f"(c[2]), "+f"(c[3])
        : "r"(a[0]), "r"(a[1]), "r"(a[2]), "r"(a[3]), "r"(b0), "r"(b1));
}

// ---------------------------------------------------------------------------
// Shared gemm helpers: weight staging + per-tile MMA/store (R13-proven)
// SMEM: sW fp16[2*OUTS][72] (18432B cap) | sX fp16[64][72] (9216B)
// ---------------------------------------------------------------------------
template <int OUTS>
__device__ __forceinline__ void stage_weights(__half* sW,
                                              const float* __restrict__ Wl,
                                              const float* __restrict__ Wr) {
    for (int idx = threadIdx.x; idx < 2 * OUTS * 64; idx += 256) {
        int n = idx >> 6, k = idx & 63;
        float wv = (n < OUTS) ? Wl[n * 64 + k] : Wr[(n - OUTS) * 64 + k];
        sW[n * 72 + k] = __float2half(wv);
    }
}

template <int OUTS>
__device__ __forceinline__ void mma_tile(const u32* sWu, const u32* sXu,
                                         const float* __restrict__ bias,
                                         __half* __restrict__ y, __half* __restrict__ z,
                                         int base, int nN) {
    const int tid  = threadIdx.x;
    const int w    = tid >> 5;
    const int lane = tid & 31;
    const int grp  = lane >> 2;
    const int tig  = lane & 3;
    const int mg   = (w & 3) * 16;
    const bool isZ = (w >= 4);
    const int nb0  = isZ ? OUTS : 0;
    constexpr int NT = OUTS / 8;

    u32 A[4][4];
    const int r0 = mg + grp;
#pragma unroll
    for (int ks = 0; ks < 4; ks++) {
        A[ks][0] = sXu[r0 * 36 + ks * 8 + tig];
        A[ks][1] = sXu[(r0 + 8) * 36 + ks * 8 + tig];
        A[ks][2] = sXu[r0 * 36 + ks * 8 + 4 + tig];
        A[ks][3] = sXu[(r0 + 8) * 36 + ks * 8 + 4 + tig];
    }

    float acc[NT][4];
#pragma unroll
    for (int nt = 0; nt < NT; nt++) {
        acc[nt][0] = 0.f; acc[nt][1] = 0.f; acc[nt][2] = 0.f; acc[nt][3] = 0.f;
        const int nrow = nb0 + nt * 8 + grp;
#pragma unroll
        for (int ks = 0; ks < 4; ks++) {
            u32 b0 = sWu[nrow * 36 + ks * 8 + tig];
            u32 b1 = sWu[nrow * 36 + ks * 8 + 4 + tig];
            mma16816(acc[nt], A[ks], b0, b1);
        }
    }

    const int m0   = base + mg + grp;
    const int ncol = tig * 2;
    const bool ok0 = (m0 < nN);
    const bool ok1 = (m0 + 8 < nN);
    if (!isZ) {
#pragma unroll
        for (int nt = 0; nt < NT; nt++) {
            const int n = nt * 8 + ncol;
            if (ok0) *(__half2*)(y + (size_t)m0 * OUTS + n) =
                __floats2half2_rn(acc[nt][0], acc[nt][1]);
            if (ok1) *(__half2*)(y + (size_t)(m0 + 8) * OUTS + n) =
                __floats2half2_rn(acc[nt][2], acc[nt][3]);
        }
    } else {
#pragma unroll
        for (int nt = 0; nt < NT; nt++) {
            const int n = nt * 8 + ncol;
            const float b0v = __ldg(&bias[n]);
            const float b1v = __ldg(&bias[n + 1]);
            if (ok0) *(__half2*)(z + (size_t)m0 * OUTS + n) =
                __floats2half2_rn(acc[nt][0] + b0v, acc[nt][1] + b1v);
            if (ok1) *(__half2*)(z + (size_t)(m0 + 8) * OUTS + n) =
                __floats2half2_rn(acc[nt][2] + b0v, acc[nt][3] + b1v);
        }
    }
}

// ---------------------------------------------------------------------------
// Layer-1 gemm body (fp32 input x, no gather)
// ---------------------------------------------------------------------------
__device__ __forceinline__ void gemm32_body(int bb, int gridB,
                                            const float4* __restrict__ xin4,
                                            const float* __restrict__ Wl,
                                            const float* __restrict__ Wr,
                                            const float* __restrict__ bias,
                                            __half* __restrict__ y, __half* __restrict__ z,
                                            int nN, unsigned char* smem) {
    __half* sW = (__half*)smem;
    __half* sX = (__half*)(smem + 18432);
    stage_weights<64>(sW, Wl, Wr);

    const int tid = threadIdx.x;
    const int gn = tid >> 2, q2 = tid & 3;
    const int nTiles = (nN + 63) >> 6;

    for (int t = bb; t < nTiles; t += gridB) {
        __syncthreads();
        const int base = t << 6;
        {
            const int node = base + gn;
            const float4* rs = xin4 + (size_t)node * 16 + q2 * 4;
            __half2 h[8];
#pragma unroll
            for (int c = 0; c < 4; c++) {
                float4 v = {0.f, 0.f, 0.f, 0.f};
                if (node < nN) v = __ldg(rs + c);
                h[c * 2]     = __floats2half2_rn(v.x, v.y);
                h[c * 2 + 1] = __floats2half2_rn(v.z, v.w);
            }
            u32* dx = (u32*)(sX + gn * 72 + q2 * 16);
#pragma unroll
            for (int c = 0; c < 8; c++) dx[c] = ((u32*)h)[c];
        }
        __syncthreads();
        mma_tile<64>((const u32*)sW, (const u32*)sX, bias, y, z, base, nN);
    }
}

// ---------------------------------------------------------------------------
// Launch 3: CSR fill (blocks [0,FB)) + layer-1 gemm (blocks [FB,FB+GB))
// ---------------------------------------------------------------------------
__launch_bounds__(256)
__global__ void fill_gemm1_kernel(const int* __restrict__ src, const int* __restrict__ dst,
                                  const int* __restrict__ start, int* __restrict__ cur,
                                  int* __restrict__ col, int E, int FB,
                                  const float4* __restrict__ xin4,
                                  const float* __restrict__ Wl, const float* __restrict__ Wr,
                                  const float* __restrict__ bias,
                                  __half* __restrict__ y, __half* __restrict__ z,
                                  int nN, int GB) {
    extern __shared__ __align__(16) unsigned char smem[];
    if (blockIdx.x < FB) {
        int e = blockIdx.x * 256 + threadIdx.x;
        if (e < E) {
            int d = dst[e];
            int p = start[d] + atomicAdd(&cur[d], 1);
            col[p] = src[e];
        }
    } else {
        gemm32_body(blockIdx.x - FB, GB, xin4, Wl, Wr, bias, y, z, nN, smem);
    }
}

// ---------------------------------------------------------------------------
// fp16 accumulate helpers (R15-proven)
// ---------------------------------------------------------------------------
__device__ __forceinline__ void acc8(float* a, uint4 v) {
    float2 f;
    f = __half22float2(*(const __half2*)&v.x); a[0] += f.x; a[1] += f.y;
    f = __half22float2(*(const __half2*)&v.y); a[2] += f.x; a[3] += f.y;
    f = __half22float2(*(const __half2*)&v.z); a[4] += f.x; a[5] += f.y;
    f = __half22float2(*(const __half2*)&v.w); a[6] += f.x; a[7] += f.y;
}
__device__ __forceinline__ uint4 hadd2v(uint4 a, uint4 b) {
    uint4 r;
    asm("add.rn.f16x2 %0, %1, %2;" : "=r"(r.x) : "r"(a.x), "r"(b.x));
    asm("add.rn.f16x2 %0, %1, %2;" : "=r"(r.y) : "r"(a.y), "r"(b.y));
    asm("add.rn.f16x2 %0, %1, %2;" : "=r"(r.z) : "r"(a.z), "r"(b.z));
    asm("add.rn.f16x2 %0, %1, %2;" : "=r"(r.w) : "r"(a.w), "r"(b.w));
    return r;
}

// ---------------------------------------------------------------------------
// Fused gather+gemm (layers 2,3): stages h = relu(mean yIn + zIn) on the fly
// into the MMA's sX, then computes yOut = fp16(h@Wl^T), zOut = fp16(h@Wr^T+b).
// Staging: 4 threads/node, each handles chunks q2 and q2+4 (2x uint4).
// Eliminates the separate gather kernel and the h round-trip entirely.
// ---------------------------------------------------------------------------
template <int OUTS>
__launch_bounds__(256)
__global__ void fused_gather_gemm_kernel(const __half* __restrict__ yIn,
                                         const __half* __restrict__ zIn,
                                         const int* __restrict__ start,
                                         const int* __restrict__ deg,
                                         const int* __restrict__ col,
                                         const float* __restrict__ Wl,
                                         const float* __restrict__ Wr,
                                         const float* __restrict__ bias,
                                         __half* __restrict__ yOut,
                                         __half* __restrict__ zOut, int nN) {
    extern __shared__ __align__(16) unsigned char smem[];
    __half* sW = (__half*)smem;
    __half* sX = (__half*)(smem + 18432);
    stage_weights<OUTS>(sW, Wl, Wr);

    const int tid = threadIdx.x;
    const int gn = tid >> 2;        // node within tile (0..63)
    const int q2 = tid & 3;         // chunks q2 and q2+4
    const int nTiles = (nN + 63) >> 6;

    for (int t = blockIdx.x; t < nTiles; t += gridDim.x) {
        __syncthreads();            // sX reuse guard (covers weight stage)
        const int base = t << 6;
        const int node = base + gn;

        uint4 h0 = {0,0,0,0}, h1 = {0,0,0,0};   // staged fp16 output chunks
        if (node < nN) {
            const int d  = __ldg(&deg[node]);
            const int p0 = __ldg(&start[node]);

            float a[16];
#pragma unroll
            for (int c = 0; c < 16; c++) a[c] = 0.f;

            int i = 0;
            for (; i + 2 <= d; i += 2) {
                int n0 = __ldg(&col[p0 + i]);
                int n1 = __ldg(&col[p0 + i + 1]);
                const uint4* r0 = (const uint4*)(yIn + (size_t)n0 * 64);
                const uint4* r1 = (const uint4*)(yIn + (size_t)n1 * 64);
                uint4 v00 = __ldg(r0 + q2), v01 = __ldg(r0 + q2 + 4);
                uint4 v10 = __ldg(r1 + q2), v11 = __ldg(r1 + q2 + 4);
                acc8(a,     hadd2v(v00, v10));
                acc8(a + 8, hadd2v(v01, v11));
            }
            if (i < d) {
                int n0 = __ldg(&col[p0 + i]);
                const uint4* r0 = (const uint4*)(yIn + (size_t)n0 * 64);
                acc8(a,     __ldg(r0 + q2));
                acc8(a + 8, __ldg(r0 + q2 + 4));
            }

            const float iv = 1.0f / fmaxf((float)d, 1.0f);
            const uint4* zr = (const uint4*)(zIn + (size_t)node * 64);
            uint4 zc0 = __ldg(zr + q2);
            uint4 zc1 = __ldg(zr + q2 + 4);
            const u32* z0 = (const u32*)&zc0;
            const u32* z1 = (const u32*)&zc1;
            u32* o0 = (u32*)&h0;
            u32* o1 = (u32*)&h1;
#pragma unroll
            for (int c = 0; c < 4; c++) {
                float2 zf0 = __half22float2(*(const __half2*)&z0[c]);
                float2 zf1 = __half22float2(*(const __half2*)&z1[c]);
                float r00 = fmaxf(a[c*2]     * iv + zf0.x, 0.f);
                float r01 = fmaxf(a[c*2+1]   * iv + zf0.y, 0.f);
                float r10 = fmaxf(a[8+c*2]   * iv + zf1.x, 0.f);
                float r11 = fmaxf(a[8+c*2+1] * iv + zf1.y, 0.f);
                *(__half2*)&o0[c] = __floats2half2_rn(r00, r01);
                *(__half2*)&o1[c] = __floats2half2_rn(r10, r11);
            }
        }
        *(uint4*)(sX + gn * 72 + q2 * 8)       = h0;
        *(uint4*)(sX + gn * 72 + (q2 + 4) * 8) = h1;
        __syncthreads();

        mma_tile<OUTS>((const u32*)sW, (const u32*)sX, bias, yOut, zOut, base, nN);
    }
}

// ---------------------------------------------------------------------------
// Final gather + fused log_softmax (40-d; 5 active chunks of 8; fp32 out)
// ---------------------------------------------------------------------------
__launch_bounds__(256)
__global__ void gather_lsm_kernel(const __half* __restrict__ y,
                                  const __half* __restrict__ z,
                                  const int* __restrict__ start,
                                  const int* __restrict__ deg,
                                  const int* __restrict__ col,
                                  float* __restrict__ out, int nN) {
    const int node = blockIdx.x * 32 + (threadIdx.x >> 3);
    const int q = threadIdx.x & 7;
    const bool valid = (node < nN) && (q < 5);

    int d = 0, p0 = 0;
    if (valid) { d = __ldg(&deg[node]); p0 = __ldg(&start[node]); }

    float a[8] = {0.f,0.f,0.f,0.f,0.f,0.f,0.f,0.f};
    int i = 0;
    for (; i + 4 <= d; i += 4) {
        int n0 = __ldg(&col[p0 + i]);
        int n1 = __ldg(&col[p0 + i + 1]);
        int n2 = __ldg(&col[p0 + i + 2]);
        int n3 = __ldg(&col[p0 + i + 3]);
        uint4 v0 = __ldg((const uint4*)(y + (size_t)n0 * 40) + q);
        uint4 v1 = __ldg((const uint4*)(y + (size_t)n1 * 40) + q);
        uint4 v2 = __ldg((const uint4*)(y + (size_t)n2 * 40) + q);
        uint4 v3 = __ldg((const uint4*)(y + (size_t)n3 * 40) + q);
        acc8(a, hadd2v(v0, v1));
        acc8(a, hadd2v(v2, v3));
    }
    for (; i < d; i++) {
        int n0 = __ldg(&col[p0 + i]);
        uint4 v0 = __ldg((const uint4*)(y + (size_t)n0 * 40) + q);
        acc8(a, v0);
    }

    float v[8];
    float m = -FLT_MAX;
    if (valid) {
        const float iv = 1.0f / fmaxf((float)d, 1.0f);
        uint4 zc = __ldg((const uint4*)(z + (size_t)node * 40) + q);
        const u32* zcu = (const u32*)&zc;
#pragma unroll
        for (int c = 0; c < 4; c++) {
            float2 zf = __half22float2(*(const __half2*)&zcu[c]);
            v[c * 2]     = a[c * 2]     * iv + zf.x;
            v[c * 2 + 1] = a[c * 2 + 1] * iv + zf.y;
        }
#pragma unroll
        for (int k2 = 0; k2 < 8; k2++) m = fmaxf(m, v[k2]);
    }
    m = fmaxf(m, __shfl_xor_sync(0xffffffffu, m, 1));
    m = fmaxf(m, __shfl_xor_sync(0xffffffffu, m, 2));
    m = fmaxf(m, __shfl_xor_sync(0xffffffffu, m, 4));

    float s = 0.f;
    if (valid) {
#pragma unroll
        for (int k2 = 0; k2 < 8; k2++) s += __expf(v[k2] - m);
    }
    s += __shfl_xor_sync(0xffffffffu, s, 1);
    s += __shfl_xor_sync(0xffffffffu, s, 2);
    s += __shfl_xor_sync(0xffffffffu, s, 4);

    if (valid) {
        const float l = m + __logf(s);
        float* orow = out + (size_t)node * 40 + q * 8;
        float4 r0, r1;
        r0.x = v[0] - l; r0.y = v[1] - l; r0.z = v[2] - l; r0.w = v[3] - l;
        r1.x = v[4] - l; r1.y = v[5] - l; r1.z = v[6] - l; r1.w = v[7] - l;
        *(float4*)orow       = r0;
        *(float4*)(orow + 4) = r1;
    }
}

// ---------------------------------------------------------------------------
// Tail: restore zero-state for next call
// ---------------------------------------------------------------------------
__global__ void tail_kernel(int* __restrict__ deg, int* __restrict__ cur,
                            int* __restrict__ pref, int n) {
    int i = blockIdx.x * blockDim.x + threadIdx.x;
    if (i < n) { deg[i] = 0; cur[i] = 0; }
    if (i < 1024) pref[i] = 0;
}

// ---------------------------------------------------------------------------
// kernel_launch — slot 4 = fused_gather_gemm<64> (the ncu-profiled launch)
// ---------------------------------------------------------------------------
extern "C" void kernel_launch(void* const* d_in, const int* in_sizes, int n_in,
                              void* d_out, int out_size) {
    const float* x   = (const float*)d_in[0];
    const int*   ei  = (const int*)d_in[1];
    const float* Wl1 = (const float*)d_in[2];
    const float* Wr1 = (const float*)d_in[3];
    const float* b1  = (const float*)d_in[4];
    const float* Wl2 = (const float*)d_in[5];
    const float* Wr2 = (const float*)d_in[6];
    const float* b2  = (const float*)d_in[7];
    const float* Wl3 = (const float*)d_in[8];
    const float* Wr3 = (const float*)d_in[9];
    const float* b3  = (const float*)d_in[10];
    float* out = (float*)d_out;

    const int N = in_sizes[0] / 64;
    const int E = in_sizes[1] / 2;
    const int* src = ei;
    const int* dst = ei + E;

    int *deg, *cur, *start, *pref, *col;
    __half *yA, *zA, *yB, *zB;
    cudaGetSymbolAddress((void**)&deg,   g_deg);
    cudaGetSymbolAddress((void**)&cur,   g_cur);
    cudaGetSymbolAddress((void**)&start, g_startArr);
    cudaGetSymbolAddress((void**)&pref,  g_pref);
    cudaGetSymbolAddress((void**)&col,   g_colArr);
    cudaGetSymbolAddress((void**)&yA,    g_y);
    cudaGetSymbolAddress((void**)&zA,    g_z);
    cudaGetSymbolAddress((void**)&yB,    g_h1);
    cudaGetSymbolAddress((void**)&zB,    g_h2);

    const int SMEM  = 18432 + 9216;   // 27.6 KB
    const int nb    = (N + 1023) / 1024;
    const int edgeB = (E + 255) / 256;
    const int GB    = 592;
    const int gathB = (N + 31) / 32;

    hist_kernel<<<edgeB, 256>>>(dst, deg, E);                       // 1
    scan_kernel<<<nb, 1024>>>(deg, start, pref, N);                 // 2
    // 3: fill + layer-1 gemm (x -> yA,zA)
    fill_gemm1_kernel<<<edgeB + GB, 256, SMEM>>>(src, dst, start, cur, col, E, edgeB,
                                                 (const float4*)x, Wl1, Wr1, b1,
                                                 yA, zA, N, GB);
    // 4 (PROFILED): layer-2 fused gather+gemm (yA,zA -> yB,zB)
    fused_gather_gemm_kernel<64><<<GB, 256, SMEM>>>(yA, zA, start, deg, col,
                                                    Wl2, Wr2, b2, yB, zB, N);
    // 5: layer-3 fused gather+gemm (yB,zB -> yA,zA as 40-wide)
    fused_gather_gemm_kernel<40><<<GB, 256, SMEM>>>(yB, zB, start, deg, col,
                                                    Wl3, Wr3, b3, yA, zA, N);
    // 6: final gather + log_softmax
    gather_lsm_kernel<<<gathB, 256>>>(yA, zA, start, deg, col, out, N);
    // 7: restore zero-state
    tail_kernel<<<(N + 255) / 256, 256>>>(deg, cur, pref, N);
}